// round 2
// baseline (speedup 1.0000x reference)
#include <cuda_runtime.h>
#include <cuda_bf16.h>

// Problem: B=8, N=1,000,000 vertices of 6 floats (pos[3], nrm[3]).
// out[...,0:3] = (T[:3,:4] @ [pos,1]) / t3  with t3 == 1 exactly (bottom row [0,0,0,1])
// out[...,3:6] = normalize(T[:3,:3] @ nrm), norm clamped to 1e-8.
// batch_indices input is unused by the reference.
//
// Memory-bound: 2 vertices (48 B) per thread = 3 float4 loads + 3 float4 stores.

static constexpr int B_ = 8;
static constexpr long long N_ = 1000000;
static constexpr int PAIRS_PER_BATCH = (int)(N_ / 2);        // 500,000
static constexpr int N_PAIRS = B_ * PAIRS_PER_BATCH;          // 4,000,000

__device__ __forceinline__ void xform_one(
    float px, float py, float pz, float nx, float ny, float nz,
    const float t00, const float t01, const float t02, const float t03,
    const float t10, const float t11, const float t12, const float t13,
    const float t20, const float t21, const float t22, const float t23,
    float& ox, float& oy, float& oz, float& mx, float& my, float& mz)
{
    // position: row_i . [p,1]   (t3 == 1 exactly, divide elided)
    ox = fmaf(t00, px, fmaf(t01, py, fmaf(t02, pz, t03)));
    oy = fmaf(t10, px, fmaf(t11, py, fmaf(t12, pz, t13)));
    oz = fmaf(t20, px, fmaf(t21, py, fmaf(t22, pz, t23)));

    // normal: R . n, then normalize with clamp
    float ux = fmaf(t00, nx, fmaf(t01, ny, t02 * nz));
    float uy = fmaf(t10, nx, fmaf(t11, ny, t12 * nz));
    float uz = fmaf(t20, nx, fmaf(t21, ny, t22 * nz));
    float s  = fmaf(ux, ux, fmaf(uy, uy, uz * uz));
    float l  = fmaxf(sqrtf(s), 1e-8f);
    float inv = 1.0f / l;
    mx = ux * inv;
    my = uy * inv;
    mz = uz * inv;
}

__global__ void __launch_bounds__(256)
vertex_xform_kernel(const float* __restrict__ verts,
                    const float* __restrict__ transforms,
                    float* __restrict__ out)
{
    int p = blockIdx.x * blockDim.x + threadIdx.x;
    if (p >= N_PAIRS) return;

    int b = p / PAIRS_PER_BATCH;

    // Load 12 transform entries (rows 0..2 of the 4x4). Warp-uniform per batch
    // (except at rare batch-boundary warps) -> L1 broadcast.
    const float* T = transforms + b * 16;
    const float t00 = __ldg(T + 0),  t01 = __ldg(T + 1),  t02 = __ldg(T + 2),  t03 = __ldg(T + 3);
    const float t10 = __ldg(T + 4),  t11 = __ldg(T + 5),  t12 = __ldg(T + 6),  t13 = __ldg(T + 7);
    const float t20 = __ldg(T + 8),  t21 = __ldg(T + 9),  t22 = __ldg(T + 10), t23 = __ldg(T + 11);

    // 2 vertices = 48 bytes = 3 x float4 (16B aligned since 48*p % 16 == 0)
    const float4* __restrict__ vin = reinterpret_cast<const float4*>(verts) + (size_t)p * 3;
    float4 a0 = vin[0];
    float4 a1 = vin[1];
    float4 a2 = vin[2];

    // vertex 0: pos = a0.xyz, nrm = (a0.w, a1.x, a1.y)
    // vertex 1: pos = (a1.z, a1.w, a2.x), nrm = a2.yzw
    float o0x, o0y, o0z, m0x, m0y, m0z;
    float o1x, o1y, o1z, m1x, m1y, m1z;

    xform_one(a0.x, a0.y, a0.z, a0.w, a1.x, a1.y,
              t00, t01, t02, t03, t10, t11, t12, t13, t20, t21, t22, t23,
              o0x, o0y, o0z, m0x, m0y, m0z);
    xform_one(a1.z, a1.w, a2.x, a2.y, a2.z, a2.w,
              t00, t01, t02, t03, t10, t11, t12, t13, t20, t21, t22, t23,
              o1x, o1y, o1z, m1x, m1y, m1z);

    float4* __restrict__ vout = reinterpret_cast<float4*>(out) + (size_t)p * 3;
    vout[0] = make_float4(o0x, o0y, o0z, m0x);
    vout[1] = make_float4(m0y, m0z, o1x, o1y);
    vout[2] = make_float4(o1z, m1x, m1y, m1z);
}

extern "C" void kernel_launch(void* const* d_in, const int* in_sizes, int n_in,
                              void* d_out, int out_size)
{
    const float* verts      = (const float*)d_in[0];  // (B, N, 6) float32
    // d_in[1] = batch_indices (unused by reference)
    const float* transforms = (const float*)d_in[2];  // (B, 4, 4) float32
    float* out = (float*)d_out;                       // (B, N, 6) float32

    const int threads = 256;
    const int blocks  = (N_PAIRS + threads - 1) / threads;
    vertex_xform_kernel<<<blocks, threads>>>(verts, transforms, out);
}